// round 6
// baseline (speedup 1.0000x reference)
#include <cuda_runtime.h>

#define FULLMASK 0xffffffffu
#define IH 256
#define IW 192

typedef unsigned long long u64;

// Gaussian taps for kernel_size=11, sigma=10/6, normalized. Indexed by |d|.
static __device__ __forceinline__ float wt(int k) {
    const float t[6] = {0.23955940f, 0.20009682f, 0.11660614f,
                        0.04740849f, 0.01344761f, 0.00266126f};
    return t[k];
}

static __device__ __forceinline__ u64 pk(float lo, float hi) {
    u64 r; asm("mov.b64 %0, {%1, %2};" : "=l"(r) : "f"(lo), "f"(hi)); return r;
}
static __device__ __forceinline__ void upk(u64 v, float& lo, float& hi) {
    asm("mov.b64 {%0, %1}, %2;" : "=f"(lo), "=f"(hi) : "l"(v));
}
static __device__ __forceinline__ u64 f2mul(u64 a, u64 b) {
    u64 d; asm("mul.rn.f32x2 %0, %1, %2;" : "=l"(d) : "l"(a), "l"(b)); return d;
}
static __device__ __forceinline__ u64 f2fma(u64 a, u64 b, u64 c) {
    u64 d; asm("fma.rn.f32x2 %0, %1, %2, %3;" : "=l"(d) : "l"(a), "l"(b), "l"(c)); return d;
}
static __device__ __forceinline__ u64 f2add(u64 a, u64 b) {
    u64 d; asm("add.rn.f32x2 %0, %1, %2;" : "=l"(d) : "l"(a), "l"(b)); return d;
}

// One step of the fused blur/argmax pipeline, prefetch distance 2.
//  U      : static slot phase (i mod 11)
//  GUARD  : head/tail mode — runtime row/load bounds checks (warp-uniform)
//  EMIT   : emit completed output row (slot U) into the running argmax
// cur holds row r (consumed now), nxt holds row r+1; loads row r+2.
template<int U, bool GUARD, bool EMIT>
static __device__ __forceinline__ void step(
    const float* __restrict__ rp,   // main-mode load base: row of U=0 load
    const float* __restrict__ ip,   // image base (GUARD-mode addressing)
    int r, int col0,
    float (&cur)[6], float (&nxt)[6], u64 (&acc)[11][3], const u64 (&w2)[6],
    bool l0, bool l31, float& bestv, int& bestlin, int ebl)
{
    // ---- load row r+2 (consumed 2 steps from now) ----
    float nn[6];
    bool loadok = true, rowok = true;
    if (GUARD) {
        loadok = ((unsigned)(r + 2) < (unsigned)IH);
        rowok  = ((unsigned)r       < (unsigned)IH);
    }
    if (loadok) {
        const float* p = GUARD ? (ip + (r + 2) * IW + col0) : (rp + U * IW);
        float2 a = *(const float2*)p;
        float2 b = *(const float2*)(p + 2);
        float2 c = *(const float2*)(p + 4);
        nn[0] = a.x; nn[1] = a.y; nn[2] = b.x;
        nn[3] = b.y; nn[4] = c.x; nn[5] = c.y;
    } else {
        nn[0] = nn[1] = nn[2] = nn[3] = nn[4] = nn[5] = 0.f;
    }

    if (rowok) {
        // halos: lo = cols col0-5..col0-1, hi = cols col0+6..col0+10
        float hl[5], hh[5];
        hl[0] = __shfl_up_sync(FULLMASK, cur[1], 1);
        hl[1] = __shfl_up_sync(FULLMASK, cur[2], 1);
        hl[2] = __shfl_up_sync(FULLMASK, cur[3], 1);
        hl[3] = __shfl_up_sync(FULLMASK, cur[4], 1);
        hl[4] = __shfl_up_sync(FULLMASK, cur[5], 1);
        hh[0] = __shfl_down_sync(FULLMASK, cur[0], 1);
        hh[1] = __shfl_down_sync(FULLMASK, cur[1], 1);
        hh[2] = __shfl_down_sync(FULLMASK, cur[2], 1);
        hh[3] = __shfl_down_sync(FULLMASK, cur[3], 1);
        hh[4] = __shfl_down_sync(FULLMASK, cur[4], 1);
        if (l0)  { hl[0]=0.f; hl[1]=0.f; hl[2]=0.f; hl[3]=0.f; hl[4]=0.f; }
        if (l31) { hh[0]=0.f; hh[1]=0.f; hh[2]=0.f; hh[3]=0.f; hh[4]=0.f; }

        // adjacent pairs over extended segment e[0..15]
        u64 P[15];
        P[0]  = pk(hl[0], hl[1]);
        P[1]  = pk(hl[1], hl[2]);
        P[2]  = pk(hl[2], hl[3]);
        P[3]  = pk(hl[3], hl[4]);
        P[4]  = pk(hl[4], cur[0]);
        P[5]  = pk(cur[0], cur[1]);
        P[6]  = pk(cur[1], cur[2]);
        P[7]  = pk(cur[2], cur[3]);
        P[8]  = pk(cur[3], cur[4]);
        P[9]  = pk(cur[4], cur[5]);
        P[10] = pk(cur[5], hh[0]);
        P[11] = pk(hh[0], hh[1]);
        P[12] = pk(hh[1], hh[2]);
        P[13] = pk(hh[2], hh[3]);
        P[14] = pk(hh[3], hh[4]);

        // horizontal blur (packed, even/odd split chains)
        u64 h2[3];
#pragma unroll
        for (int j = 0; j < 3; ++j) {
            u64 sa = f2mul(P[2*j + 0], w2[5]);
            sa = f2fma(P[2*j + 2],  w2[3], sa);
            sa = f2fma(P[2*j + 4],  w2[1], sa);
            sa = f2fma(P[2*j + 6],  w2[1], sa);
            sa = f2fma(P[2*j + 8],  w2[3], sa);
            sa = f2fma(P[2*j + 10], w2[5], sa);
            u64 sb = f2mul(P[2*j + 1], w2[4]);
            sb = f2fma(P[2*j + 3],  w2[2], sb);
            sb = f2fma(P[2*j + 5],  w2[0], sb);
            sb = f2fma(P[2*j + 7],  w2[2], sb);
            sb = f2fma(P[2*j + 9],  w2[4], sb);
            h2[j] = f2add(sa, sb);
        }

        // vertical taps: k=0..9 accumulate, k=10 overwrites recycled slot
#pragma unroll
        for (int k = 0; k < 10; ++k) {
            const u64 wv = w2[k <= 5 ? 5 - k : k - 5];
            const int s = (U + k) % 11;
            acc[s][0] = f2fma(h2[0], wv, acc[s][0]);
            acc[s][1] = f2fma(h2[1], wv, acc[s][1]);
            acc[s][2] = f2fma(h2[2], wv, acc[s][2]);
        }
        {
            const int s = (U + 10) % 11;
            acc[s][0] = f2mul(h2[0], w2[5]);
            acc[s][1] = f2mul(h2[1], w2[5]);
            acc[s][2] = f2mul(h2[2], w2[5]);
        }
    } else {
        const int s = (U + 10) % 11;
        acc[s][0] = 0ull; acc[s][1] = 0ull; acc[s][2] = 0ull;
    }

    if (EMIT) {
        float a0, a1, a2, a3, a4, a5;
        upk(acc[U][0], a0, a1);
        upk(acc[U][1], a2, a3);
        upk(acc[U][2], a4, a5);
        const float m01 = fmaxf(a0, a1);
        const float m23 = fmaxf(a2, a3);
        const float m45 = fmaxf(a4, a5);
        const float rowmax = fmaxf(fmaxf(m01, m23), m45);
        if (rowmax > bestv) {           // rare
            bestv = rowmax;
            int c = 5;
            if (a4 == rowmax) c = 4;
            if (a3 == rowmax) c = 3;
            if (a2 == rowmax) c = 2;
            if (a1 == rowmax) c = 1;
            if (a0 == rowmax) c = 0;
            bestlin = ebl + U * IW + c;
        }
    }

    // rotate (renamed away by full unroll)
#pragma unroll
    for (int c = 0; c < 6; ++c) { cur[c] = nxt[c]; nxt[c] = nn[c]; }
}

// One CTA (64 threads = 2 warps) per (b,k) image; warp w owns output rows
// [w*128, w*128+128), lane owns 6 columns. Head (11 guarded) + main
// (10x11 branch-free) + tail (17 guarded).
__global__ __launch_bounds__(64, 7)
void dark_decode_kernel(const float* __restrict__ hm,
                        float* __restrict__ out, int n_img)
{
    const int img  = blockIdx.x;
    const int warp = threadIdx.x >> 5;
    const int lane = threadIdx.x & 31;
    const float* __restrict__ ip = hm + (long long)img * (IH * IW);
    const int base = warp * 128;
    const int col0 = lane * 6;
    const bool l0  = (lane == 0);
    const bool l31 = (lane == 31);

    u64 w2[6];
#pragma unroll
    for (int k = 0; k < 6; ++k) w2[k] = pk(wt(k), wt(k));

    u64 acc[11][3];   // no init needed: every slot is overwritten before emit

    float cur[6], nxt[6];
    {   // rows base-5 and base-4 (warp0: OOB -> zeros)
        const int r0 = base - 5;
        if (r0 >= 0) {
            const float* p = ip + r0 * IW + col0;
            float2 a = *(const float2*)p;
            float2 b = *(const float2*)(p + 2);
            float2 c = *(const float2*)(p + 4);
            cur[0]=a.x; cur[1]=a.y; cur[2]=b.x; cur[3]=b.y; cur[4]=c.x; cur[5]=c.y;
        } else {
#pragma unroll
            for (int c = 0; c < 6; ++c) cur[c] = 0.f;
        }
        const int r1 = base - 4;
        if (r1 >= 0) {
            const float* p = ip + r1 * IW + col0;
            float2 a = *(const float2*)p;
            float2 b = *(const float2*)(p + 2);
            float2 c = *(const float2*)(p + 4);
            nxt[0]=a.x; nxt[1]=a.y; nxt[2]=b.x; nxt[3]=b.y; nxt[4]=c.x; nxt[5]=c.y;
        } else {
#pragma unroll
            for (int c = 0; c < 6; ++c) nxt[c] = 0.f;
        }
    }

    float bestv   = -3.4e38f;
    int   bestlin = 0;

    // ---- head: i = 0..10 (r = base-5+i), guarded; emit only at i=10 ----
    {
        const int eblh = (base - 10) * IW + col0;
#define HSTEP(U, EM) step<U, true, EM>(ip, ip, base - 5 + (U), col0, cur, nxt, \
                                       acc, w2, l0, l31, bestv, bestlin, eblh)
        HSTEP(0, false); HSTEP(1, false); HSTEP(2, false); HSTEP(3, false);
        HSTEP(4, false); HSTEP(5, false); HSTEP(6, false); HSTEP(7, false);
        HSTEP(8, false); HSTEP(9, false); HSTEP(10, true);
#undef HSTEP
    }

    // ---- main: i = 11..120, 10 blocks x 11 steps, branch-free ----
    // step i loads row r+2 = base-3+i ; at ib=0,U=0 (i=11) -> row base+8
    {
        const float* rp = ip + (base + 8) * IW + col0;
        int ebl = (base + 1) * IW + col0;               // ro at ib=0,U=0
#define MSTEP(U) step<U, false, true>(rp, ip, 0, col0, cur, nxt, acc, w2, \
                                      l0, l31, bestv, bestlin, ebl)
        for (int ib = 0; ib < 10; ++ib) {
            MSTEP(0); MSTEP(1); MSTEP(2); MSTEP(3); MSTEP(4); MSTEP(5);
            MSTEP(6); MSTEP(7); MSTEP(8); MSTEP(9); MSTEP(10);
            rp  += 11 * IW;
            ebl += 11 * IW;
        }
#undef MSTEP
    }

    // ---- tail: i = 121..137, guarded, always emit ----
    // i=121..131 -> U=0..10 (ro = base+111+U); i=132..137 -> U=0..5
    {
        const int eblt1 = (base + 111) * IW + col0;
#define T1STEP(U) step<U, true, true>(ip, ip, base + 116 + (U), col0, cur, nxt, \
                                      acc, w2, l0, l31, bestv, bestlin, eblt1)
        T1STEP(0); T1STEP(1); T1STEP(2); T1STEP(3); T1STEP(4); T1STEP(5);
        T1STEP(6); T1STEP(7); T1STEP(8); T1STEP(9); T1STEP(10);
#undef T1STEP
        const int eblt2 = (base + 122) * IW + col0;
#define T2STEP(U) step<U, true, true>(ip, ip, base + 127 + (U), col0, cur, nxt, \
                                      acc, w2, l0, l31, bestv, bestlin, eblt2)
        T2STEP(0); T2STEP(1); T2STEP(2); T2STEP(3); T2STEP(4); T2STEP(5);
#undef T2STEP
    }

    // intra-warp argmax reduce (larger value wins; tie -> smaller linear index)
#pragma unroll
    for (int off = 16; off >= 1; off >>= 1) {
        const float ov = __shfl_xor_sync(FULLMASK, bestv, off);
        const int   oi = __shfl_xor_sync(FULLMASK, bestlin, off);
        if (ov > bestv || (ov == bestv && oi < bestlin)) { bestv = ov; bestlin = oi; }
    }

    __shared__ float s_v[2];
    __shared__ int   s_i[2];
    if (lane == 0) { s_v[warp] = bestv; s_i[warp] = bestlin; }
    __syncthreads();
    if (warp != 0) return;

    float fv; int fl;
    {
        const float v0 = s_v[0], v1 = s_v[1];
        const int   i0 = s_i[0], i1 = s_i[1];
        if (v1 > v0 || (v1 == v0 && i1 < i0)) { fv = v1; fl = i1; }
        else                                  { fv = v0; fl = i0; }
    }
    const int py = fl / IW;
    const int px = fl - py * IW;

    float offx = 0.f, offy = 0.f;
    const bool bok = (px >= 1) && (px < IW - 1) && (py >= 1) && (py < IH - 1);
    if (bok) {
        // 39 hblur values: flat j in [0,39), rr = py-6 + j/3, cc = px-1 + j%3
        float h0 = 0.f, h1 = 0.f;
        {
            int j = lane;
            int rr = py - 6 + j / 3;
            int cc = px - 1 + (j - (j / 3) * 3);
            if (rr >= 0 && rr < IH) {
                const float* rp2 = ip + rr * IW;
                float s = 0.f;
#pragma unroll
                for (int d = -5; d <= 5; ++d) {
                    const int c = cc + d;
                    float v = 0.f;
                    if ((unsigned)c < (unsigned)IW) v = rp2[c];
                    s += v * wt(d < 0 ? -d : d);
                }
                h0 = s;
            }
            j = lane + 32;
            if (j < 39) {
                rr = py - 6 + j / 3;
                cc = px - 1 + (j - (j / 3) * 3);
                if (rr >= 0 && rr < IH) {
                    const float* rp2 = ip + rr * IW;
                    float s = 0.f;
#pragma unroll
                    for (int d = -5; d <= 5; ++d) {
                        const int c = cc + d;
                        float v = 0.f;
                        if ((unsigned)c < (unsigned)IW) v = rp2[c];
                        s += v * wt(d < 0 ? -d : d);
                    }
                    h1 = s;
                }
            }
        }
        // lanes 0..8: vertical blur -> patch entry p(a,b), a=lane/3, b=lane%3
        const int a = lane / 3;
        const int b = lane - a * 3;
        float p = 0.f;
#pragma unroll
        for (int t = 0; t < 11; ++t) {
            const int j = (a + t) * 3 + b;
            const float va = __shfl_sync(FULLMASK, h0, j & 31);
            const float vb = __shfl_sync(FULLMASK, h1, j & 31);
            const float hv = (j < 32) ? va : vb;
            p += hv * wt(t <= 5 ? 5 - t : t - 5);
        }
        const float p00 = __shfl_sync(FULLMASK, p, 0);
        const float p01 = __shfl_sync(FULLMASK, p, 1);
        const float p02 = __shfl_sync(FULLMASK, p, 2);
        const float p10 = __shfl_sync(FULLMASK, p, 3);
        const float p11 = __shfl_sync(FULLMASK, p, 4);
        const float p12 = __shfl_sync(FULLMASK, p, 5);
        const float p20 = __shfl_sync(FULLMASK, p, 6);
        const float p21 = __shfl_sync(FULLMASK, p, 7);
        const float p22 = __shfl_sync(FULLMASK, p, 8);

        const float dx  = (p12 - p10) * 0.5f;
        const float dy  = (p21 - p01) * 0.5f;
        const float dxx = p12 - 2.f * p11 + p10;
        const float dyy = p21 - 2.f * p11 + p01;
        const float dxy = (p22 - p20 - p02 + p00) * 0.25f;
        const float det = dxx * dyy - dxy * dxy;
        if (fabsf(det) >= 1e-6f && dxx < 0.f) {
            const float ox = -(dyy * dx - dxy * dy) / det;
            const float oy = -(dxx * dy - dxy * dx) / det;
            offx = fminf(fmaxf(ox, -0.5f), 0.5f);
            offy = fminf(fmaxf(oy, -0.5f), 0.5f);
        }
    }

    if (lane == 0) {
        const float xo = fminf(fmaxf((float)px + offx, 0.f), (float)(IW - 1));
        const float yo = fminf(fmaxf((float)py + offy, 0.f), (float)(IH - 1));
        out[2 * img + 0] = xo;                       // coords[...,0] = x
        out[2 * img + 1] = yo;                       // coords[...,1] = y
        out[(long long)2 * n_img + img] = fv;        // max_vals
    }
}

extern "C" void kernel_launch(void* const* d_in, const int* in_sizes, int n_in,
                              void* d_out, int out_size)
{
    const float* hm = (const float*)d_in[0];
    // d_in[1] is kernel_size (always 11 in this problem; taps are baked in)
    const int n_img = in_sizes[0] / (IH * IW);
    dark_decode_kernel<<<n_img, 64>>>(hm, (float*)d_out, n_img);
}